// round 15
// baseline (speedup 1.0000x reference)
#include <cuda_runtime.h>
#include <cuda_bf16.h>
#include <math.h>

#define BB 16384
#define PRED 12

typedef unsigned long long ull;

// ---------------- scratch (device globals; no allocation allowed) ----------
__device__ float g_gates[BB * 512];          // per-step LSTM gates
__device__ float g_h[BB * 128];              // hidden state
__device__ float g_c[BB * 128];              // cell state
__device__ float g_Wt[128 * 512];            // transposed W_hh  [k][n]
__device__ float g_M[2 * 512];               // W_emb @ W_ih^T   [i][n]
__device__ float g_Mb[512];                  // b_emb@W_ih^T + b_ih + b_hh

__device__ __forceinline__ float sigm(float x) { return 1.f / (1.f + expf(-x)); }

// packed f32x2 helpers (sm_103a)
#define FMA2(d, a, b)  asm("fma.rn.f32x2 %0, %1, %2, %0;" : "+l"(d) : "l"(a), "l"(b))
#define ADD2(d, a)     asm("add.rn.f32x2 %0, %0, %1;"     : "+l"(d) : "l"(a))
#define DUP2F(o, x)    asm("mov.b64 %0, {%1, %1};" : "=l"(o) : "r"(__float_as_uint(x)))
#define DUP2U(o, x)    asm("mov.b64 %0, {%1, %1};" : "=l"(o) : "r"(x))
#define UNPKU(lo, hi, in) asm("mov.b64 {%0, %1}, %2;" : "=r"(lo), "=r"(hi) : "l"(in))
#define UNPKF(lo, hi, in) asm("mov.b64 {%0, %1}, %2;" : "=f"(lo), "=f"(hi) : "l"(in))
#define PACKF(o, lo, hi)  asm("mov.b64 %0, {%1, %2};" : "=l"(o) : "f"(lo), "f"(hi))

// ---------------- prep kernels ---------------------------------------------
__global__ void prep_wt(const float* __restrict__ Whh) {
    int idx = blockIdx.x * blockDim.x + threadIdx.x;   // < 128*512
    int k = idx >> 9, n = idx & 511;
    g_Wt[idx] = Whh[n * 128 + k];
}

__global__ void prep_M(const float* __restrict__ We, const float* __restrict__ be,
                       const float* __restrict__ Wih, const float* __restrict__ bih,
                       const float* __restrict__ bhh) {
    int n = blockIdx.x * blockDim.x + threadIdx.x;     // < 512
    float m0 = 0.f, m1 = 0.f, mb = 0.f;
    const float* wr = Wih + n * 64;
#pragma unroll 8
    for (int f = 0; f < 64; f++) {
        float w = wr[f];
        m0 += We[f] * w;
        m1 += We[64 + f] * w;
        mb += be[f] * w;
    }
    g_M[n] = m0; g_M[512 + n] = m1;
    g_Mb[n] = mb + bih[n] + bhh[n];
}

__global__ void prep_init(const float* __restrict__ h0) {
    int i = blockIdx.x * 256 + threadIdx.x;
    if (i < BB * 128) { g_h[i] = h0[i]; g_c[i] = 0.f; }
}

// ---------------- LSTM gates GEMM: C = h(16384x128) @ Wt(128x512) ----------
// + rank-2 input term a0*M0[n] + a1*M1[n] + Mb[n] in epilogue. f32x2 FMA.
// Double-buffered smem: 1 barrier per K-chunk; next-chunk LDGs overlap compute.
__global__ __launch_bounds__(256) void gemm_gates(int t, const float* __restrict__ arow) {
    __shared__ float As[2][16 * 128];
    __shared__ float Bs[2][16 * 128];
    __shared__ float Ms[3 * 128];
    int tid = threadIdx.x;
    int m0 = blockIdx.y * 128;
    int n0 = blockIdx.x * 128;
    int tx = tid & 15, ty = tid >> 4;

    if (tid < 128) {
        Ms[tid]       = g_M[n0 + tid];
        Ms[128 + tid] = g_M[512 + n0 + tid];
        Ms[256 + tid] = g_Mb[n0 + tid];
    }

    ull acc2[8][4];
#pragma unroll
    for (int i = 0; i < 8; i++)
#pragma unroll
        for (int j = 0; j < 4; j++) acc2[i][j] = 0ull;

    int arr = tid >> 2;           // 0..63 (rows arr, arr+64)
    int akq = (tid & 3) * 4;      // k-subcolumn
    int bkk = tid >> 4;           // 0..15
    int bn4 = (tid & 15) * 4;     // 0..60
    const float* aptr = arow + ((size_t)(8 + t) * BB) * 2;

    // ---- preload chunk 0 into buffer 0 ----
    {
        float4 a0 = *(const float4*)(g_h + (size_t)(m0 + arr) * 128 + akq);
        float4 a1 = *(const float4*)(g_h + (size_t)(m0 + arr + 64) * 128 + akq);
        float4 b0 = *(const float4*)(g_Wt + bkk * 512 + n0 + bn4);
        float4 b1 = *(const float4*)(g_Wt + bkk * 512 + n0 + 64 + bn4);
        As[0][(akq + 0) * 128 + arr] = a0.x;  As[0][(akq + 1) * 128 + arr] = a0.y;
        As[0][(akq + 2) * 128 + arr] = a0.z;  As[0][(akq + 3) * 128 + arr] = a0.w;
        As[0][(akq + 0) * 128 + arr + 64] = a1.x;  As[0][(akq + 1) * 128 + arr + 64] = a1.y;
        As[0][(akq + 2) * 128 + arr + 64] = a1.z;  As[0][(akq + 3) * 128 + arr + 64] = a1.w;
        *(float4*)&Bs[0][bkk * 128 + bn4]      = b0;
        *(float4*)&Bs[0][bkk * 128 + 64 + bn4] = b1;
    }
    __syncthreads();   // buffer-0 stores + Ms visible to all

#pragma unroll
    for (int kc = 0; kc < 8; kc++) {
        int buf = kc & 1;
        float4 na0, na1, nb0, nb1;
        if (kc < 7) {
            int k0 = (kc + 1) * 16;
            na0 = *(const float4*)(g_h + (size_t)(m0 + arr) * 128 + k0 + akq);
            na1 = *(const float4*)(g_h + (size_t)(m0 + arr + 64) * 128 + k0 + akq);
            nb0 = *(const float4*)(g_Wt + (k0 + bkk) * 512 + n0 + bn4);
            nb1 = *(const float4*)(g_Wt + (k0 + bkk) * 512 + n0 + 64 + bn4);
        }
#pragma unroll
        for (int kk = 0; kk < 16; kk++) {
            float4 t0 = *(const float4*)&As[buf][kk * 128 + ty * 4];
            float4 t1 = *(const float4*)&As[buf][kk * 128 + ty * 4 + 64];
            ulonglong2 ub0 = *(const ulonglong2*)&Bs[buf][kk * 128 + tx * 4];
            ulonglong2 ub1 = *(const ulonglong2*)&Bs[buf][kk * 128 + 64 + tx * 4];
            ull av[8];
            DUP2F(av[0], t0.x); DUP2F(av[1], t0.y); DUP2F(av[2], t0.z); DUP2F(av[3], t0.w);
            DUP2F(av[4], t1.x); DUP2F(av[5], t1.y); DUP2F(av[6], t1.z); DUP2F(av[7], t1.w);
#pragma unroll
            for (int i = 0; i < 8; i++) {
                FMA2(acc2[i][0], av[i], ub0.x);
                FMA2(acc2[i][1], av[i], ub0.y);
                FMA2(acc2[i][2], av[i], ub1.x);
                FMA2(acc2[i][3], av[i], ub1.y);
            }
        }
        if (kc < 7) {
            int nb = buf ^ 1;
            As[nb][(akq + 0) * 128 + arr] = na0.x;  As[nb][(akq + 1) * 128 + arr] = na0.y;
            As[nb][(akq + 2) * 128 + arr] = na0.z;  As[nb][(akq + 3) * 128 + arr] = na0.w;
            As[nb][(akq + 0) * 128 + arr + 64] = na1.x;  As[nb][(akq + 1) * 128 + arr + 64] = na1.y;
            As[nb][(akq + 2) * 128 + arr + 64] = na1.z;  As[nb][(akq + 3) * 128 + arr + 64] = na1.w;
            *(float4*)&Bs[nb][bkk * 128 + bn4]      = nb0;
            *(float4*)&Bs[nb][bkk * 128 + 64 + bn4] = nb1;
            __syncthreads();
        }
    }

    ull m0p[4], m1p[4], mbp[4];
#pragma unroll
    for (int jh = 0; jh < 2; jh++)
#pragma unroll
        for (int jq = 0; jq < 2; jq++) {
            int c = jh * 64 + tx * 4 + jq * 2;
            m0p[jh * 2 + jq] = *(const ull*)&Ms[c];
            m1p[jh * 2 + jq] = *(const ull*)&Ms[128 + c];
            mbp[jh * 2 + jq] = *(const ull*)&Ms[256 + c];
        }
#pragma unroll
    for (int ih = 0; ih < 2; ih++)
#pragma unroll
        for (int i = 0; i < 4; i++) {
            int m = m0 + ty * 4 + ih * 64 + i;
            int ai = ih * 4 + i;
            float2 av = *(const float2*)(aptr + (size_t)m * 2);
            ull a0d, a1d;
            DUP2F(a0d, av.x); DUP2F(a1d, av.y);
#pragma unroll
            for (int j = 0; j < 4; j++) {
                FMA2(acc2[ai][j], a0d, m0p[j]);
                FMA2(acc2[ai][j], a1d, m1p[j]);
                ADD2(acc2[ai][j], mbp[j]);
            }
            *(ulonglong2*)(g_gates + (size_t)m * 512 + n0 + tx * 4) =
                make_ulonglong2(acc2[ai][0], acc2[ai][1]);
            *(ulonglong2*)(g_gates + (size_t)m * 512 + n0 + 64 + tx * 4) =
                make_ulonglong2(acc2[ai][2], acc2[ai][3]);
        }
}

// ---------------- fused LSTM + goal-softmax + 2-layer GAT ------------------
// 512 blocks x 128 threads; warp w handles group blockIdx.x*4 + w entirely.
// Goal mask computed inline (softmax over 128 cols per agent, warp shuffles).
#define GAT_SMEM_FLOATS 26516
__global__ __launch_bounds__(128) void gat_step(
    int t, const float* __restrict__ pgg,
    const float* __restrict__ Wgg,  const float* __restrict__ bgg,
    const float* __restrict__ w1g,  const float* __restrict__ as1g,
    const float* __restrict__ ad1g, const float* __restrict__ b1g,
    const float* __restrict__ w2g,  const float* __restrict__ as2g,
    const float* __restrict__ ad2g, const float* __restrict__ b2g,
    const float* __restrict__ Wpg,  const float* __restrict__ bpg,
    float* __restrict__ out)
{
    extern __shared__ float sm[];
    int tid = threadIdx.x;
    int w = tid >> 5, l = tid & 31;

    for (int i = tid; i < 8192; i += 128) sm[i] = w1g[i];
    for (int i = tid; i < 8192; i += 128) sm[8192 + i] = w2g[i];
    if (tid < 64) { sm[16384 + tid] = as1g[tid]; sm[16448 + tid] = ad1g[tid]; }
    if (tid < 16) sm[16512 + tid] = b1g[tid];
    if (tid < 128) { sm[16528 + tid] = as2g[tid]; sm[16656 + tid] = ad2g[tid]; sm[16784 + tid] = b2g[tid]; }
    for (int i = tid; i < 256; i += 128) sm[16912 + i] = Wpg[i];
    if (tid < 2) sm[17168 + tid] = bpg[tid];
    for (int i = tid; i < 256; i += 128) sm[26132 + i] = Wgg[i];
    sm[26388 + tid] = bgg[tid];
    __syncthreads();

    const float* w1s = sm;
    const float* w2s = sm + 8192;
    const float* as1 = sm + 16384;
    const float* ad1 = sm + 16448;
    const float* b1s = sm + 16512;
    const float* as2 = sm + 16528;
    const float* ad2 = sm + 16656;
    const float* b2s = sm + 16784;
    const float* Wps = sm + 16912;
    const float* bps = sm + 17168;
    float* hsT  = sm + 17172 + w * 1280;
    float* xsT  = sm + 22292 + w * 640;
    float* at1s = sm + 24852 + w * 256;
    float* at2s = sm + 25876 + w * 64;
    const float* Wgs = sm + 26132;   // [2][128]
    const float* bgs = sm + 26388;   // [128]

    int Gi = blockIdx.x * 4 + w;
    int rbase = Gi * 8;

    // ---- Phase 1: LSTM activations + inline goal softmax -> hsT[f][n] -----
    {
        const float* pgp = pgg + ((size_t)t * BB + rbase) * 2;
#pragma unroll
        for (int n = 0; n < 8; n++) {
            int R = rbase + n;
            float p0 = pgp[n * 2], p1 = pgp[n * 2 + 1];
            float v[4]; float mx = -1e30f;
#pragma unroll
            for (int q = 0; q < 4; q++) {
                int f = (q << 5) + l;
                v[q] = p0 * Wgs[f] + p1 * Wgs[128 + f] + bgs[f];
                mx = fmaxf(mx, v[q]);
            }
#pragma unroll
            for (int off = 16; off; off >>= 1) mx = fmaxf(mx, __shfl_xor_sync(~0u, mx, off));
            float sum = 0.f;
#pragma unroll
            for (int q = 0; q < 4; q++) { v[q] = expf(v[q] - mx); sum += v[q]; }
#pragma unroll
            for (int off = 16; off; off >>= 1) sum += __shfl_xor_sync(~0u, sum, off);
            float inv = 1.f / sum;

            const float* gp = g_gates + (size_t)R * 512;
#pragma unroll
            for (int q = 0; q < 4; q++) {
                int f = (q << 5) + l;
                float gi_ = gp[f], gf = gp[128 + f], gg = gp[256 + f], go = gp[384 + f];
                float c_old = g_c[R * 128 + f];
                float cn = sigm(gf) * c_old + sigm(gi_) * tanhf(gg);
                float hn = sigm(go) * tanhf(cn);
                g_c[R * 128 + f] = cn;
                hsT[f * 10 + n] = hn * (v[q] * inv);
            }
        }
    }
    __syncwarp();

    // ---- Phase 2: proj1  P2[np][oq] = f32x2 over agent-pairs --------------
    int k = l >> 3, op = l & 7;
    ull P2[4][2];
#pragma unroll
    for (int i = 0; i < 4; i++) { P2[i][0] = 0ull; P2[i][1] = 0ull; }
    {
        const float* wbase = w1s + k * 2048 + (op << 1);
#pragma unroll 8
        for (int f = 0; f < 128; f++) {
            ull wp = *(const ull*)&wbase[f * 16];
            unsigned int wlo, whi; UNPKU(wlo, whi, wp);
            ull w0d, w1d; DUP2U(w0d, wlo); DUP2U(w1d, whi);
            ull h0 = *(const ull*)&hsT[f * 10 + 0];
            ull h1 = *(const ull*)&hsT[f * 10 + 2];
            ull h2 = *(const ull*)&hsT[f * 10 + 4];
            ull h3 = *(const ull*)&hsT[f * 10 + 6];
            FMA2(P2[0][0], h0, w0d); FMA2(P2[0][1], h0, w1d);
            FMA2(P2[1][0], h1, w0d); FMA2(P2[1][1], h1, w1d);
            FMA2(P2[2][0], h2, w0d); FMA2(P2[2][1], h2, w1d);
            FMA2(P2[3][0], h3, w0d); FMA2(P2[3][1], h3, w1d);
        }
    }

    // ---- Phase 3: attn1 ---------------------------------------------------
    {
        ull sp[4] = {0,0,0,0}, dp[4] = {0,0,0,0};
        float a0 = as1[k * 16 + (op << 1)],     a1 = as1[k * 16 + (op << 1) + 1];
        float c0 = ad1[k * 16 + (op << 1)],     c1 = ad1[k * 16 + (op << 1) + 1];
        ull a0d, a1d, c0d, c1d;
        DUP2F(a0d, a0); DUP2F(a1d, a1); DUP2F(c0d, c0); DUP2F(c1d, c1);
#pragma unroll
        for (int np = 0; np < 4; np++) {
            FMA2(sp[np], P2[np][0], a0d); FMA2(sp[np], P2[np][1], a1d);
            FMA2(dp[np], P2[np][0], c0d); FMA2(dp[np], P2[np][1], c1d);
        }
        float s[8], d[8];
#pragma unroll
        for (int np = 0; np < 4; np++) {
            UNPKF(s[2 * np], s[2 * np + 1], sp[np]);
            UNPKF(d[2 * np], d[2 * np + 1], dp[np]);
        }
#pragma unroll
        for (int off = 1; off < 8; off <<= 1)
#pragma unroll
            for (int i = 0; i < 8; i++) {
                s[i] += __shfl_xor_sync(~0u, s[i], off);
                d[i] += __shfl_xor_sync(~0u, d[i], off);
            }
        float sn = s[0];
#pragma unroll
        for (int m = 1; m < 8; m++) if (op == m) sn = s[m];
        float e[8]; float mx = -1e30f;
#pragma unroll
        for (int m = 0; m < 8; m++) {
            float a = sn + d[m];
            a = a > 0.f ? a : 0.2f * a;
            e[m] = a; mx = fmaxf(mx, a);
        }
        float sum = 0.f;
#pragma unroll
        for (int m = 0; m < 8; m++) { e[m] = expf(e[m] - mx); sum += e[m]; }
        float inv = 1.f / sum;
#pragma unroll
        for (int m = 0; m < 8; m++) at1s[k * 64 + op * 8 + m] = e[m] * inv;
    }
    __syncwarp();

    // ---- Phase 4: y1 = attn1 @ hp1 + b1, ELU -> xsT[f][n] -----------------
    {
        float b1lo = b1s[(op << 1)], b1hi = b1s[(op << 1) + 1];
        int f0 = k * 16 + (op << 1);
#pragma unroll
        for (int n = 0; n < 8; n++) {
            ull ap0 = *(const ull*)&at1s[k * 64 + n * 8 + 0];
            ull ap1 = *(const ull*)&at1s[k * 64 + n * 8 + 2];
            ull ap2 = *(const ull*)&at1s[k * 64 + n * 8 + 4];
            ull ap3 = *(const ull*)&at1s[k * 64 + n * 8 + 6];
            ull Y0 = 0ull, Y1 = 0ull;
            FMA2(Y0, P2[0][0], ap0); FMA2(Y1, P2[0][1], ap0);
            FMA2(Y0, P2[1][0], ap1); FMA2(Y1, P2[1][1], ap1);
            FMA2(Y0, P2[2][0], ap2); FMA2(Y1, P2[2][1], ap2);
            FMA2(Y0, P2[3][0], ap3); FMA2(Y1, P2[3][1], ap3);
            float y0a, y0b, y1a, y1b;
            UNPKF(y0a, y0b, Y0); UNPKF(y1a, y1b, Y1);
            float y0 = y0a + y0b + b1lo;
            float y1 = y1a + y1b + b1hi;
            y0 = y0 > 0.f ? y0 : (expf(y0) - 1.f);
            y1 = y1 > 0.f ? y1 : (expf(y1) - 1.f);
            xsT[f0 * 10 + n]       = y0;
            xsT[(f0 + 1) * 10 + n] = y1;
        }
    }
    __syncwarp();

    // ---- Phase 5: proj2  Q2[np][oi], o = {2l, 2l+1, 64+2l, 65+2l} ---------
    int o0 = l << 1;
    ull Q2[4][4];
#pragma unroll
    for (int i = 0; i < 4; i++)
#pragma unroll
        for (int j = 0; j < 4; j++) Q2[i][j] = 0ull;
#pragma unroll 4
    for (int f = 0; f < 64; f++) {
        ull wl = *(const ull*)&w2s[f * 128 + o0];
        ull wh = *(const ull*)&w2s[f * 128 + 64 + o0];
        unsigned int u0, u1, u2, u3;
        UNPKU(u0, u1, wl); UNPKU(u2, u3, wh);
        ull wd0, wd1, wd2, wd3;
        DUP2U(wd0, u0); DUP2U(wd1, u1); DUP2U(wd2, u2); DUP2U(wd3, u3);
        ull x0 = *(const ull*)&xsT[f * 10 + 0];
        ull x1 = *(const ull*)&xsT[f * 10 + 2];
        ull x2 = *(const ull*)&xsT[f * 10 + 4];
        ull x3 = *(const ull*)&xsT[f * 10 + 6];
        FMA2(Q2[0][0], x0, wd0); FMA2(Q2[0][1], x0, wd1); FMA2(Q2[0][2], x0, wd2); FMA2(Q2[0][3], x0, wd3);
        FMA2(Q2[1][0], x1, wd0); FMA2(Q2[1][1], x1, wd1); FMA2(Q2[1][2], x1, wd2); FMA2(Q2[1][3], x1, wd3);
        FMA2(Q2[2][0], x2, wd0); FMA2(Q2[2][1], x2, wd1); FMA2(Q2[2][2], x2, wd2); FMA2(Q2[2][3], x2, wd3);
        FMA2(Q2[3][0], x3, wd0); FMA2(Q2[3][1], x3, wd1); FMA2(Q2[3][2], x3, wd2); FMA2(Q2[3][3], x3, wd3);
    }

    // ---- Phase 6: attn2 ---------------------------------------------------
    {
        ull sp[4] = {0,0,0,0}, dp[4] = {0,0,0,0};
        float av[4] = { as2[o0], as2[o0 + 1], as2[64 + o0], as2[65 + o0] };
        float cv[4] = { ad2[o0], ad2[o0 + 1], ad2[64 + o0], ad2[65 + o0] };
#pragma unroll
        for (int oi = 0; oi < 4; oi++) {
            ull avd, cvd; DUP2F(avd, av[oi]); DUP2F(cvd, cv[oi]);
#pragma unroll
            for (int np = 0; np < 4; np++) {
                FMA2(sp[np], Q2[np][oi], avd);
                FMA2(dp[np], Q2[np][oi], cvd);
            }
        }
        float s[8], d[8];
#pragma unroll
        for (int np = 0; np < 4; np++) {
            UNPKF(s[2 * np], s[2 * np + 1], sp[np]);
            UNPKF(d[2 * np], d[2 * np + 1], dp[np]);
        }
#pragma unroll
        for (int off = 1; off < 32; off <<= 1)
#pragma unroll
            for (int i = 0; i < 8; i++) {
                s[i] += __shfl_xor_sync(~0u, s[i], off);
                d[i] += __shfl_xor_sync(~0u, d[i], off);
            }
        if (l < 8) {
            float sn = s[0];
#pragma unroll
            for (int m = 1; m < 8; m++) if (l == m) sn = s[m];
            float e[8]; float mx = -1e30f;
#pragma unroll
            for (int m = 0; m < 8; m++) {
                float a = sn + d[m];
                a = a > 0.f ? a : 0.2f * a;
                e[m] = a; mx = fmaxf(mx, a);
            }
            float sum = 0.f;
#pragma unroll
            for (int m = 0; m < 8; m++) { e[m] = expf(e[m] - mx); sum += e[m]; }
            float inv = 1.f / sum;
#pragma unroll
            for (int m = 0; m < 8; m++) at2s[l * 8 + m] = e[m] * inv;
        }
    }
    __syncwarp();

    // ---- Phase 7: hnew = attn2 @ hp2 + b2; write g_h; position head -------
    {
        ull Wp[4];
        Wp[0] = *(const ull*)&Wps[o0 * 2];
        Wp[1] = *(const ull*)&Wps[(o0 + 1) * 2];
        Wp[2] = *(const ull*)&Wps[(64 + o0) * 2];
        Wp[3] = *(const ull*)&Wps[(65 + o0) * 2];
        float b2v[4] = { b2s[o0], b2s[o0 + 1], b2s[64 + o0], b2s[65 + o0] };
        ull opn[8];
#pragma unroll
        for (int n = 0; n < 8; n++) opn[n] = 0ull;

#pragma unroll
        for (int n = 0; n < 8; n++) {
            ull ap0 = *(const ull*)&at2s[n * 8 + 0];
            ull ap1 = *(const ull*)&at2s[n * 8 + 2];
            ull ap2 = *(const ull*)&at2s[n * 8 + 4];
            ull ap3 = *(const ull*)&at2s[n * 8 + 6];
            float hnv[4];
#pragma unroll
            for (int oi = 0; oi < 4; oi++) {
                ull H = 0ull;
                FMA2(H, Q2[0][oi], ap0);
                FMA2(H, Q2[1][oi], ap1);
                FMA2(H, Q2[2][oi], ap2);
                FMA2(H, Q2[3][oi], ap3);
                float hlo, hhi; UNPKF(hlo, hhi, H);
                hnv[oi] = hlo + hhi + b2v[oi];
            }
            ull plo, phi;
            PACKF(plo, hnv[0], hnv[1]);
            PACKF(phi, hnv[2], hnv[3]);
            *(ull*)&g_h[(size_t)(rbase + n) * 128 + o0]      = plo;
            *(ull*)&g_h[(size_t)(rbase + n) * 128 + 64 + o0] = phi;
#pragma unroll
            for (int oi = 0; oi < 4; oi++) {
                ull hd; DUP2F(hd, hnv[oi]);
                FMA2(opn[n], hd, Wp[oi]);
            }
        }
#pragma unroll
        for (int off = 1; off < 32; off <<= 1)
#pragma unroll
            for (int n = 0; n < 8; n++) {
                ull other = __shfl_xor_sync(~0u, opn[n], off);
                ADD2(opn[n], other);
            }
        if (l < 8) {
            ull mine = opn[0];
#pragma unroll
            for (int m = 1; m < 8; m++) if (l == m) mine = opn[m];
            float p0v, p1v; UNPKF(p0v, p1v, mine);
            float2 res = make_float2(p0v + bps[0], p1v + bps[1]);
            *(float2*)&out[((size_t)t * BB + rbase + l) * 2] = res;
        }
    }
}

// ---------------- launch ----------------------------------------------------
extern "C" void kernel_launch(void* const* d_in, const int* in_sizes, int n_in,
                              void* d_out, int out_size) {
    const float* action_real = (const float*)d_in[0];
    const float* h0          = (const float*)d_in[1];
    const float* pred_goal   = (const float*)d_in[2];
    // d_in[3] seq_start_end (uniform groups of 8) and d_in[4] teacher_forcing unused
    const float* W_emb  = (const float*)d_in[5];
    const float* b_emb  = (const float*)d_in[6];
    const float* W_ih   = (const float*)d_in[7];
    const float* W_hh   = (const float*)d_in[8];
    const float* b_ih   = (const float*)d_in[9];
    const float* b_hh   = (const float*)d_in[10];
    const float* W_goal = (const float*)d_in[11];
    const float* b_goal = (const float*)d_in[12];
    const float* w1     = (const float*)d_in[13];
    const float* a_src1 = (const float*)d_in[14];
    const float* a_dst1 = (const float*)d_in[15];
    const float* bias1  = (const float*)d_in[16];
    const float* w2     = (const float*)d_in[17];
    const float* a_src2 = (const float*)d_in[18];
    const float* a_dst2 = (const float*)d_in[19];
    const float* bias2  = (const float*)d_in[20];
    const float* W_pos  = (const float*)d_in[21];
    const float* b_pos  = (const float*)d_in[22];
    float* out = (float*)d_out;

    size_t gat_smem = GAT_SMEM_FLOATS * sizeof(float);
    cudaFuncSetAttribute(gat_step, cudaFuncAttributeMaxDynamicSharedMemorySize, (int)gat_smem);

    prep_wt  <<<(128 * 512) / 256, 256>>>(W_hh);
    prep_M   <<<2, 256>>>(W_emb, b_emb, W_ih, b_ih, b_hh);
    prep_init<<<BB * 128 / 256, 256>>>(h0);

    for (int t = 0; t < PRED; t++) {
        gemm_gates<<<dim3(4, 128), 256>>>(t, action_real);
        gat_step<<<512, 128, gat_smem>>>(t, pred_goal, W_goal, b_goal,
                                         w1, a_src1, a_dst1, bias1,
                                         w2, a_src2, a_dst2, bias2,
                                         W_pos, b_pos, out);
    }
}

// round 16
// speedup vs baseline: 1.2365x; 1.2365x over previous
#include <cuda_runtime.h>
#include <cuda_bf16.h>
#include <math.h>

#define BB 16384
#define PRED 12

typedef unsigned long long ull;

// ---------------- scratch (device globals; no allocation allowed) ----------
__device__ float g_gates[BB * 512];          // per-step LSTM gates
__device__ float g_h[BB * 128];              // hidden state
__device__ float g_c[BB * 128];              // cell state
__device__ float g_Wt[128 * 512];            // transposed W_hh  [k][n]
__device__ float g_M[2 * 512];               // W_emb @ W_ih^T   [i][n]
__device__ float g_Mb[512];                  // b_emb@W_ih^T + b_ih + b_hh

__device__ __forceinline__ float sigm(float x) { return 1.f / (1.f + expf(-x)); }

// packed f32x2 helpers (sm_103a)
#define FMA2(d, a, b)  asm("fma.rn.f32x2 %0, %1, %2, %0;" : "+l"(d) : "l"(a), "l"(b))
#define ADD2(d, a)     asm("add.rn.f32x2 %0, %0, %1;"     : "+l"(d) : "l"(a))
#define DUP2F(o, x)    asm("mov.b64 %0, {%1, %1};" : "=l"(o) : "r"(__float_as_uint(x)))
#define DUP2U(o, x)    asm("mov.b64 %0, {%1, %1};" : "=l"(o) : "r"(x))
#define UNPKU(lo, hi, in) asm("mov.b64 {%0, %1}, %2;" : "=r"(lo), "=r"(hi) : "l"(in))
#define UNPKF(lo, hi, in) asm("mov.b64 {%0, %1}, %2;" : "=f"(lo), "=f"(hi) : "l"(in))
#define PACKF(o, lo, hi)  asm("mov.b64 %0, {%1, %2};" : "=l"(o) : "f"(lo), "f"(hi))

// ---------------- prep kernels ---------------------------------------------
__global__ void prep_wt(const float* __restrict__ Whh) {
    int idx = blockIdx.x * blockDim.x + threadIdx.x;   // < 128*512
    int k = idx >> 9, n = idx & 511;
    g_Wt[idx] = Whh[n * 128 + k];
}

__global__ void prep_M(const float* __restrict__ We, const float* __restrict__ be,
                       const float* __restrict__ Wih, const float* __restrict__ bih,
                       const float* __restrict__ bhh) {
    int n = blockIdx.x * blockDim.x + threadIdx.x;     // < 512
    float m0 = 0.f, m1 = 0.f, mb = 0.f;
    const float* wr = Wih + n * 64;
#pragma unroll 8
    for (int f = 0; f < 64; f++) {
        float w = wr[f];
        m0 += We[f] * w;
        m1 += We[64 + f] * w;
        mb += be[f] * w;
    }
    g_M[n] = m0; g_M[512 + n] = m1;
    g_Mb[n] = mb + bih[n] + bhh[n];
}

__global__ void prep_init(const float* __restrict__ h0) {
    int i = blockIdx.x * 256 + threadIdx.x;
    if (i < BB * 128) { g_h[i] = h0[i]; g_c[i] = 0.f; }
}

// ---------------- LSTM gates GEMM: C = h(16384x128) @ Wt(128x512) ----------
// Tile 64x128, grid (4,256)=1024 blocks, acc 4x4 packed pairs -> ~80 regs,
// 3 blocks/SM (24 warps) vs old 2 (16). Double-buffered, 1 barrier/chunk.
// Rank-2 input term a0*M0[n] + a1*M1[n] + Mb[n] folded into epilogue.
__global__ __launch_bounds__(256) void gemm_gates(int t, const float* __restrict__ arow) {
    __shared__ float As[2][16 * 64];
    __shared__ float Bs[2][16 * 128];
    __shared__ float Ms[3 * 128];
    int tid = threadIdx.x;
    int m0 = blockIdx.y * 64;
    int n0 = blockIdx.x * 128;
    int tx = tid & 15, ty = tid >> 4;

    if (tid < 128) {
        Ms[tid]       = g_M[n0 + tid];
        Ms[128 + tid] = g_M[512 + n0 + tid];
        Ms[256 + tid] = g_Mb[n0 + tid];
    }

    ull acc2[4][4];
#pragma unroll
    for (int i = 0; i < 4; i++)
#pragma unroll
        for (int j = 0; j < 4; j++) acc2[i][j] = 0ull;

    int arr = tid >> 2;           // 0..63 (A row)
    int akq = (tid & 3) * 4;      // k-subcolumn
    int bkk = tid >> 4;           // 0..15
    int bn4 = (tid & 15) * 4;     // 0..60
    const float* aptr = arow + ((size_t)(8 + t) * BB) * 2;

    // ---- preload chunk 0 into buffer 0 ----
    {
        float4 a0 = *(const float4*)(g_h + (size_t)(m0 + arr) * 128 + akq);
        float4 b0 = *(const float4*)(g_Wt + bkk * 512 + n0 + bn4);
        float4 b1 = *(const float4*)(g_Wt + bkk * 512 + n0 + 64 + bn4);
        As[0][(akq + 0) * 64 + arr] = a0.x;  As[0][(akq + 1) * 64 + arr] = a0.y;
        As[0][(akq + 2) * 64 + arr] = a0.z;  As[0][(akq + 3) * 64 + arr] = a0.w;
        *(float4*)&Bs[0][bkk * 128 + bn4]      = b0;
        *(float4*)&Bs[0][bkk * 128 + 64 + bn4] = b1;
    }
    __syncthreads();   // buffer-0 stores + Ms visible to all

#pragma unroll
    for (int kc = 0; kc < 8; kc++) {
        int buf = kc & 1;
        float4 na0, nb0, nb1;
        if (kc < 7) {
            int k0 = (kc + 1) * 16;
            na0 = *(const float4*)(g_h + (size_t)(m0 + arr) * 128 + k0 + akq);
            nb0 = *(const float4*)(g_Wt + (k0 + bkk) * 512 + n0 + bn4);
            nb1 = *(const float4*)(g_Wt + (k0 + bkk) * 512 + n0 + 64 + bn4);
        }
#pragma unroll
        for (int kk = 0; kk < 16; kk++) {
            float4 t0 = *(const float4*)&As[buf][kk * 64 + ty * 4];
            ulonglong2 ub0 = *(const ulonglong2*)&Bs[buf][kk * 128 + tx * 4];
            ulonglong2 ub1 = *(const ulonglong2*)&Bs[buf][kk * 128 + 64 + tx * 4];
            ull av[4];
            DUP2F(av[0], t0.x); DUP2F(av[1], t0.y); DUP2F(av[2], t0.z); DUP2F(av[3], t0.w);
#pragma unroll
            for (int i = 0; i < 4; i++) {
                FMA2(acc2[i][0], av[i], ub0.x);
                FMA2(acc2[i][1], av[i], ub0.y);
                FMA2(acc2[i][2], av[i], ub1.x);
                FMA2(acc2[i][3], av[i], ub1.y);
            }
        }
        if (kc < 7) {
            int nb = buf ^ 1;
            As[nb][(akq + 0) * 64 + arr] = na0.x;  As[nb][(akq + 1) * 64 + arr] = na0.y;
            As[nb][(akq + 2) * 64 + arr] = na0.z;  As[nb][(akq + 3) * 64 + arr] = na0.w;
            *(float4*)&Bs[nb][bkk * 128 + bn4]      = nb0;
            *(float4*)&Bs[nb][bkk * 128 + 64 + bn4] = nb1;
            __syncthreads();
        }
    }

    ull m0p[4], m1p[4], mbp[4];
#pragma unroll
    for (int jh = 0; jh < 2; jh++)
#pragma unroll
        for (int jq = 0; jq < 2; jq++) {
            int c = jh * 64 + tx * 4 + jq * 2;
            m0p[jh * 2 + jq] = *(const ull*)&Ms[c];
            m1p[jh * 2 + jq] = *(const ull*)&Ms[128 + c];
            mbp[jh * 2 + jq] = *(const ull*)&Ms[256 + c];
        }
#pragma unroll
    for (int i = 0; i < 4; i++) {
        int m = m0 + ty * 4 + i;
        float2 av = *(const float2*)(aptr + (size_t)m * 2);
        ull a0d, a1d;
        DUP2F(a0d, av.x); DUP2F(a1d, av.y);
#pragma unroll
        for (int j = 0; j < 4; j++) {
            FMA2(acc2[i][j], a0d, m0p[j]);
            FMA2(acc2[i][j], a1d, m1p[j]);
            ADD2(acc2[i][j], mbp[j]);
        }
        *(ulonglong2*)(g_gates + (size_t)m * 512 + n0 + tx * 4) =
            make_ulonglong2(acc2[i][0], acc2[i][1]);
        *(ulonglong2*)(g_gates + (size_t)m * 512 + n0 + 64 + tx * 4) =
            make_ulonglong2(acc2[i][2], acc2[i][3]);
    }
}

// ---------------- fused LSTM + goal-softmax + 2-layer GAT ------------------
// 512 blocks x 128 threads; warp w handles group blockIdx.x*4 + w entirely.
// w1/w2 weights read directly from global (L1-cached) -> smem 40.5KB/block,
// 4 blocks/SM (16 warps) vs old 2 (8); single wave.
#define GAT_SMEM_FLOATS 10132
__global__ __launch_bounds__(128, 4) void gat_step(
    int t, const float* __restrict__ pgg,
    const float* __restrict__ Wgg,  const float* __restrict__ bgg,
    const float* __restrict__ w1g,  const float* __restrict__ as1g,
    const float* __restrict__ ad1g, const float* __restrict__ b1g,
    const float* __restrict__ w2g,  const float* __restrict__ as2g,
    const float* __restrict__ ad2g, const float* __restrict__ b2g,
    const float* __restrict__ Wpg,  const float* __restrict__ bpg,
    float* __restrict__ out)
{
    extern __shared__ float sm[];
    int tid = threadIdx.x;
    int w = tid >> 5, l = tid & 31;

    if (tid < 64) { sm[tid] = as1g[tid]; sm[64 + tid] = ad1g[tid]; }
    if (tid < 16) sm[128 + tid] = b1g[tid];
    if (tid < 128) { sm[144 + tid] = as2g[tid]; sm[272 + tid] = ad2g[tid]; sm[400 + tid] = b2g[tid]; }
    for (int i = tid; i < 256; i += 128) sm[528 + i] = Wpg[i];
    if (tid < 2) sm[784 + tid] = bpg[tid];
    for (int i = tid; i < 256; i += 128) sm[788 + i] = Wgg[i];
    sm[1044 + tid] = bgg[tid];
    __syncthreads();

    const float* as1 = sm;
    const float* ad1 = sm + 64;
    const float* b1s = sm + 128;
    const float* as2 = sm + 144;
    const float* ad2 = sm + 272;
    const float* b2s = sm + 400;
    const float* Wps = sm + 528;
    const float* bps = sm + 784;
    const float* Wgs = sm + 788;    // [2][128]
    const float* bgs = sm + 1044;   // [128]
    float* hsT  = sm + 1172 + w * 1280;
    float* xsT  = sm + 6292 + w * 640;
    float* at1s = sm + 8852 + w * 256;
    float* at2s = sm + 9876 + w * 64;

    int Gi = blockIdx.x * 4 + w;
    int rbase = Gi * 8;

    // ---- Phase 1: LSTM activations + inline goal softmax -> hsT[f][n] -----
    {
        const float* pgp = pgg + ((size_t)t * BB + rbase) * 2;
#pragma unroll
        for (int n = 0; n < 8; n++) {
            int R = rbase + n;
            float p0 = pgp[n * 2], p1 = pgp[n * 2 + 1];
            float v[4]; float mx = -1e30f;
#pragma unroll
            for (int q = 0; q < 4; q++) {
                int f = (q << 5) + l;
                v[q] = p0 * Wgs[f] + p1 * Wgs[128 + f] + bgs[f];
                mx = fmaxf(mx, v[q]);
            }
#pragma unroll
            for (int off = 16; off; off >>= 1) mx = fmaxf(mx, __shfl_xor_sync(~0u, mx, off));
            float sum = 0.f;
#pragma unroll
            for (int q = 0; q < 4; q++) { v[q] = expf(v[q] - mx); sum += v[q]; }
#pragma unroll
            for (int off = 16; off; off >>= 1) sum += __shfl_xor_sync(~0u, sum, off);
            float inv = 1.f / sum;

            const float* gp = g_gates + (size_t)R * 512;
#pragma unroll
            for (int q = 0; q < 4; q++) {
                int f = (q << 5) + l;
                float gi_ = gp[f], gf = gp[128 + f], gg = gp[256 + f], go = gp[384 + f];
                float c_old = g_c[R * 128 + f];
                float cn = sigm(gf) * c_old + sigm(gi_) * tanhf(gg);
                float hn = sigm(go) * tanhf(cn);
                g_c[R * 128 + f] = cn;
                hsT[f * 10 + n] = hn * (v[q] * inv);
            }
        }
    }
    __syncwarp();

    // ---- Phase 2: proj1  P2[np][oq]; w1 read from global (L1) -------------
    int k = l >> 3, op = l & 7;
    ull P2[4][2];
#pragma unroll
    for (int i = 0; i < 4; i++) { P2[i][0] = 0ull; P2[i][1] = 0ull; }
    {
        const float* wbase = w1g + k * 2048 + (op << 1);
#pragma unroll 8
        for (int f = 0; f < 128; f++) {
            ull wp = *(const ull*)(wbase + f * 16);
            unsigned int wlo, whi; UNPKU(wlo, whi, wp);
            ull w0d, w1d; DUP2U(w0d, wlo); DUP2U(w1d, whi);
            ull h0 = *(const ull*)&hsT[f * 10 + 0];
            ull h1 = *(const ull*)&hsT[f * 10 + 2];
            ull h2 = *(const ull*)&hsT[f * 10 + 4];
            ull h3 = *(const ull*)&hsT[f * 10 + 6];
            FMA2(P2[0][0], h0, w0d); FMA2(P2[0][1], h0, w1d);
            FMA2(P2[1][0], h1, w0d); FMA2(P2[1][1], h1, w1d);
            FMA2(P2[2][0], h2, w0d); FMA2(P2[2][1], h2, w1d);
            FMA2(P2[3][0], h3, w0d); FMA2(P2[3][1], h3, w1d);
        }
    }

    // ---- Phase 3: attn1 ---------------------------------------------------
    {
        ull sp[4] = {0,0,0,0}, dp[4] = {0,0,0,0};
        float a0 = as1[k * 16 + (op << 1)],     a1 = as1[k * 16 + (op << 1) + 1];
        float c0 = ad1[k * 16 + (op << 1)],     c1 = ad1[k * 16 + (op << 1) + 1];
        ull a0d, a1d, c0d, c1d;
        DUP2F(a0d, a0); DUP2F(a1d, a1); DUP2F(c0d, c0); DUP2F(c1d, c1);
#pragma unroll
        for (int np = 0; np < 4; np++) {
            FMA2(sp[np], P2[np][0], a0d); FMA2(sp[np], P2[np][1], a1d);
            FMA2(dp[np], P2[np][0], c0d); FMA2(dp[np], P2[np][1], c1d);
        }
        float s[8], d[8];
#pragma unroll
        for (int np = 0; np < 4; np++) {
            UNPKF(s[2 * np], s[2 * np + 1], sp[np]);
            UNPKF(d[2 * np], d[2 * np + 1], dp[np]);
        }
#pragma unroll
        for (int off = 1; off < 8; off <<= 1)
#pragma unroll
            for (int i = 0; i < 8; i++) {
                s[i] += __shfl_xor_sync(~0u, s[i], off);
                d[i] += __shfl_xor_sync(~0u, d[i], off);
            }
        float sn = s[0];
#pragma unroll
        for (int m = 1; m < 8; m++) if (op == m) sn = s[m];
        float e[8]; float mx = -1e30f;
#pragma unroll
        for (int m = 0; m < 8; m++) {
            float a = sn + d[m];
            a = a > 0.f ? a : 0.2f * a;
            e[m] = a; mx = fmaxf(mx, a);
        }
        float sum = 0.f;
#pragma unroll
        for (int m = 0; m < 8; m++) { e[m] = expf(e[m] - mx); sum += e[m]; }
        float inv = 1.f / sum;
#pragma unroll
        for (int m = 0; m < 8; m++) at1s[k * 64 + op * 8 + m] = e[m] * inv;
    }
    __syncwarp();

    // ---- Phase 4: y1 = attn1 @ hp1 + b1, ELU -> xsT[f][n] -----------------
    {
        float b1lo = b1s[(op << 1)], b1hi = b1s[(op << 1) + 1];
        int f0 = k * 16 + (op << 1);
#pragma unroll
        for (int n = 0; n < 8; n++) {
            ull ap0 = *(const ull*)&at1s[k * 64 + n * 8 + 0];
            ull ap1 = *(const ull*)&at1s[k * 64 + n * 8 + 2];
            ull ap2 = *(const ull*)&at1s[k * 64 + n * 8 + 4];
            ull ap3 = *(const ull*)&at1s[k * 64 + n * 8 + 6];
            ull Y0 = 0ull, Y1 = 0ull;
            FMA2(Y0, P2[0][0], ap0); FMA2(Y1, P2[0][1], ap0);
            FMA2(Y0, P2[1][0], ap1); FMA2(Y1, P2[1][1], ap1);
            FMA2(Y0, P2[2][0], ap2); FMA2(Y1, P2[2][1], ap2);
            FMA2(Y0, P2[3][0], ap3); FMA2(Y1, P2[3][1], ap3);
            float y0a, y0b, y1a, y1b;
            UNPKF(y0a, y0b, Y0); UNPKF(y1a, y1b, Y1);
            float y0 = y0a + y0b + b1lo;
            float y1 = y1a + y1b + b1hi;
            y0 = y0 > 0.f ? y0 : (expf(y0) - 1.f);
            y1 = y1 > 0.f ? y1 : (expf(y1) - 1.f);
            xsT[f0 * 10 + n]       = y0;
            xsT[(f0 + 1) * 10 + n] = y1;
        }
    }
    __syncwarp();

    // ---- Phase 5: proj2  Q2[np][oi]; w2 read from global (L1) -------------
    int o0 = l << 1;
    ull Q2[4][4];
#pragma unroll
    for (int i = 0; i < 4; i++)
#pragma unroll
        for (int j = 0; j < 4; j++) Q2[i][j] = 0ull;
#pragma unroll 4
    for (int f = 0; f < 64; f++) {
        ull wl = *(const ull*)(w2g + f * 128 + o0);
        ull wh = *(const ull*)(w2g + f * 128 + 64 + o0);
        unsigned int u0, u1, u2, u3;
        UNPKU(u0, u1, wl); UNPKU(u2, u3, wh);
        ull wd0, wd1, wd2, wd3;
        DUP2U(wd0, u0); DUP2U(wd1, u1); DUP2U(wd2, u2); DUP2U(wd3, u3);
        ull x0 = *(const ull*)&xsT[f * 10 + 0];
        ull x1 = *(const ull*)&xsT[f * 10 + 2];
        ull x2 = *(const ull*)&xsT[f * 10 + 4];
        ull x3 = *(const ull*)&xsT[f * 10 + 6];
        FMA2(Q2[0][0], x0, wd0); FMA2(Q2[0][1], x0, wd1); FMA2(Q2[0][2], x0, wd2); FMA2(Q2[0][3], x0, wd3);
        FMA2(Q2[1][0], x1, wd0); FMA2(Q2[1][1], x1, wd1); FMA2(Q2[1][2], x1, wd2); FMA2(Q2[1][3], x1, wd3);
        FMA2(Q2[2][0], x2, wd0); FMA2(Q2[2][1], x2, wd1); FMA2(Q2[2][2], x2, wd2); FMA2(Q2[2][3], x2, wd3);
        FMA2(Q2[3][0], x3, wd0); FMA2(Q2[3][1], x3, wd1); FMA2(Q2[3][2], x3, wd2); FMA2(Q2[3][3], x3, wd3);
    }

    // ---- Phase 6: attn2 ---------------------------------------------------
    {
        ull sp[4] = {0,0,0,0}, dp[4] = {0,0,0,0};
        float av[4] = { as2[o0], as2[o0 + 1], as2[64 + o0], as2[65 + o0] };
        float cv[4] = { ad2[o0], ad2[o0 + 1], ad2[64 + o0], ad2[65 + o0] };
#pragma unroll
        for (int oi = 0; oi < 4; oi++) {
            ull avd, cvd; DUP2F(avd, av[oi]); DUP2F(cvd, cv[oi]);
#pragma unroll
            for (int np = 0; np < 4; np++) {
                FMA2(sp[np], Q2[np][oi], avd);
                FMA2(dp[np], Q2[np][oi], cvd);
            }
        }
        float s[8], d[8];
#pragma unroll
        for (int np = 0; np < 4; np++) {
            UNPKF(s[2 * np], s[2 * np + 1], sp[np]);
            UNPKF(d[2 * np], d[2 * np + 1], dp[np]);
        }
#pragma unroll
        for (int off = 1; off < 32; off <<= 1)
#pragma unroll
            for (int i = 0; i < 8; i++) {
                s[i] += __shfl_xor_sync(~0u, s[i], off);
                d[i] += __shfl_xor_sync(~0u, d[i], off);
            }
        if (l < 8) {
            float sn = s[0];
#pragma unroll
            for (int m = 1; m < 8; m++) if (l == m) sn = s[m];
            float e[8]; float mx = -1e30f;
#pragma unroll
            for (int m = 0; m < 8; m++) {
                float a = sn + d[m];
                a = a > 0.f ? a : 0.2f * a;
                e[m] = a; mx = fmaxf(mx, a);
            }
            float sum = 0.f;
#pragma unroll
            for (int m = 0; m < 8; m++) { e[m] = expf(e[m] - mx); sum += e[m]; }
            float inv = 1.f / sum;
#pragma unroll
            for (int m = 0; m < 8; m++) at2s[l * 8 + m] = e[m] * inv;
        }
    }
    __syncwarp();

    // ---- Phase 7: hnew = attn2 @ hp2 + b2; write g_h; position head -------
    {
        ull Wp[4];
        Wp[0] = *(const ull*)&Wps[o0 * 2];
        Wp[1] = *(const ull*)&Wps[(o0 + 1) * 2];
        Wp[2] = *(const ull*)&Wps[(64 + o0) * 2];
        Wp[3] = *(const ull*)&Wps[(65 + o0) * 2];
        float b2v[4] = { b2s[o0], b2s[o0 + 1], b2s[64 + o0], b2s[65 + o0] };
        ull opn[8];
#pragma unroll
        for (int n = 0; n < 8; n++) opn[n] = 0ull;

#pragma unroll
        for (int n = 0; n < 8; n++) {
            ull ap0 = *(const ull*)&at2s[n * 8 + 0];
            ull ap1 = *(const ull*)&at2s[n * 8 + 2];
            ull ap2 = *(const ull*)&at2s[n * 8 + 4];
            ull ap3 = *(const ull*)&at2s[n * 8 + 6];
            float hnv[4];
#pragma unroll
            for (int oi = 0; oi < 4; oi++) {
                ull H = 0ull;
                FMA2(H, Q2[0][oi], ap0);
                FMA2(H, Q2[1][oi], ap1);
                FMA2(H, Q2[2][oi], ap2);
                FMA2(H, Q2[3][oi], ap3);
                float hlo, hhi; UNPKF(hlo, hhi, H);
                hnv[oi] = hlo + hhi + b2v[oi];
            }
            ull plo, phi;
            PACKF(plo, hnv[0], hnv[1]);
            PACKF(phi, hnv[2], hnv[3]);
            *(ull*)&g_h[(size_t)(rbase + n) * 128 + o0]      = plo;
            *(ull*)&g_h[(size_t)(rbase + n) * 128 + 64 + o0] = phi;
#pragma unroll
            for (int oi = 0; oi < 4; oi++) {
                ull hd; DUP2F(hd, hnv[oi]);
                FMA2(opn[n], hd, Wp[oi]);
            }
        }
#pragma unroll
        for (int off = 1; off < 32; off <<= 1)
#pragma unroll
            for (int n = 0; n < 8; n++) {
                ull other = __shfl_xor_sync(~0u, opn[n], off);
                ADD2(opn[n], other);
            }
        if (l < 8) {
            ull mine = opn[0];
#pragma unroll
            for (int m = 1; m < 8; m++) if (l == m) mine = opn[m];
            float p0v, p1v; UNPKF(p0v, p1v, mine);
            float2 res = make_float2(p0v + bps[0], p1v + bps[1]);
            *(float2*)&out[((size_t)t * BB + rbase + l) * 2] = res;
        }
    }
}

// ---------------- launch ----------------------------------------------------
extern "C" void kernel_launch(void* const* d_in, const int* in_sizes, int n_in,
                              void* d_out, int out_size) {
    const float* action_real = (const float*)d_in[0];
    const float* h0          = (const float*)d_in[1];
    const float* pred_goal   = (const float*)d_in[2];
    // d_in[3] seq_start_end (uniform groups of 8) and d_in[4] teacher_forcing unused
    const float* W_emb  = (const float*)d_in[5];
    const float* b_emb  = (const float*)d_in[6];
    const float* W_ih   = (const float*)d_in[7];
    const float* W_hh   = (const float*)d_in[8];
    const float* b_ih   = (const float*)d_in[9];
    const float* b_hh   = (const float*)d_in[10];
    const float* W_goal = (const float*)d_in[11];
    const float* b_goal = (const float*)d_in[12];
    const float* w1     = (const float*)d_in[13];
    const float* a_src1 = (const float*)d_in[14];
    const float* a_dst1 = (const float*)d_in[15];
    const float* bias1  = (const float*)d_in[16];
    const float* w2     = (const float*)d_in[17];
    const float* a_src2 = (const float*)d_in[18];
    const float* a_dst2 = (const float*)d_in[19];
    const float* bias2  = (const float*)d_in[20];
    const float* W_pos  = (const float*)d_in[21];
    const float* b_pos  = (const float*)d_in[22];
    float* out = (float*)d_out;

    size_t gat_smem = GAT_SMEM_FLOATS * sizeof(float);
    cudaFuncSetAttribute(gat_step, cudaFuncAttributeMaxDynamicSharedMemorySize, (int)gat_smem);

    prep_wt  <<<(128 * 512) / 256, 256>>>(W_hh);
    prep_M   <<<2, 256>>>(W_emb, b_emb, W_ih, b_ih, b_hh);
    prep_init<<<BB * 128 / 256, 256>>>(h0);

    for (int t = 0; t < PRED; t++) {
        gemm_gates<<<dim3(4, 256), 256>>>(t, action_real);
        gat_step<<<512, 128, gat_smem>>>(t, pred_goal, W_goal, b_goal,
                                         w1, a_src1, a_dst1, bias1,
                                         w2, a_src2, a_dst2, bias2,
                                         W_pos, b_pos, out);
    }
}